// round 4
// baseline (speedup 1.0000x reference)
#include <cuda_runtime.h>

// ---------------------------------------------------------------------------
// Att_mask: per batch item b (65536 of them):
//   Q = tanh(Aq @ x_b), K = tanh(Ak @ x_b), V = tanh(Av @ x_b)   ([32,16] each)
//   scores = Q K^T / sqrt(nn_b); attn = softmax(scores, axis=s)
//   o = attn @ V ; R = tanh(Ao @ o)  ([16])
//   out row (b = s*16+i): out[b,j] = (j==i) ? sum_j R2[j] : -R2[j],  R2 = R^2
//
// Strategy: one warp per batch item (lane = rank r), packed f32x2 FFMA
// (fma.rn.f32x2 -> FFMA2, 2x fp32 throughput), A matrices transposed in
// shared (conflict-free lane reads), x/K/V staged in per-warp shared.
// Online softmax (|score| <= 16 so exp never overflows; no max pass, no
// 32-register score array).
// ---------------------------------------------------------------------------

typedef unsigned long long u64;

__device__ __forceinline__ u64 ff2(u64 a, u64 b, u64 c) {
    u64 d; asm("fma.rn.f32x2 %0, %1, %2, %3;" : "=l"(d) : "l"(a), "l"(b), "l"(c)); return d;
}
__device__ __forceinline__ u64 mul2(u64 a, u64 b) {
    u64 d; asm("mul.rn.f32x2 %0, %1, %2;" : "=l"(d) : "l"(a), "l"(b)); return d;
}
__device__ __forceinline__ u64 dup2(float a) {
    u64 d; asm("mov.b64 %0, {%1, %1};" : "=l"(d) : "f"(a)); return d;
}
__device__ __forceinline__ float2 un2(u64 a) {
    float2 f; asm("mov.b64 {%0, %1}, %2;" : "=f"(f.x), "=f"(f.y) : "l"(a)); return f;
}
__device__ __forceinline__ u64 pk2(float x, float y) {
    u64 d; asm("mov.b64 %0, {%1, %2};" : "=l"(d) : "f"(x), "f"(y)); return d;
}
__device__ __forceinline__ float tanh_approx(float x) {
    float y; asm("tanh.approx.f32 %0, %1;" : "=f"(y) : "f"(x)); return y;
}

static constexpr int WARPS = 8;     // warps per block
static constexpr int NB    = 4;     // batch items per warp
// shared layout (floats):
//   sAq[64*32] sAk[64*32] sAv[64*32] sAo[32]   = 6176
//   per warp: x[64*16]=1024, K[32*18]=576, V[32*18]=576  -> 2176
static constexpr int A_FLOATS  = 3 * 2048 + 32;       // 6176
static constexpr int PW_FLOATS = 1024 + 576 + 576;    // 2176
static constexpr int SMEM_BYTES = (A_FLOATS + WARPS * PW_FLOATS) * 4;  // 94336

__global__ void __launch_bounds__(WARPS * 32, 2)
att_mask_kernel(const float* __restrict__ x, const float* __restrict__ L,
                const float* __restrict__ Aq, const float* __restrict__ Ak,
                const float* __restrict__ Av, const float* __restrict__ Ao,
                float* __restrict__ out)
{
    extern __shared__ float smem[];
    float* sAq = smem;            // [64][32], sAq[d*32+r] = Aq[r*64+d]
    float* sAk = smem + 2048;
    float* sAv = smem + 4096;
    float* sAo = smem + 6144;     // [32]

    const int tid = threadIdx.x;

    // Load A transposed: conflict-free broadcast-free lane-indexed reads later.
    for (int i = tid; i < 2048; i += WARPS * 32) {
        int d = i >> 5, r = i & 31;
        sAq[i] = Aq[r * 64 + d];
        sAk[i] = Ak[r * 64 + d];
        sAv[i] = Av[r * 64 + d];
    }
    if (tid < 32) sAo[tid] = Ao[tid];
    __syncthreads();

    const int w    = tid >> 5;
    const int lane = tid & 31;

    float* sx = smem + A_FLOATS + w * PW_FLOATS;   // [64][16]
    float* sK = sx + 1024;                         // [32] rows, stride 18
    float* sV = sK + 576;                          // [32] rows, stride 18

    const float aor = sAo[lane];

    for (int jj = 0; jj < NB; jj++) {
        const int b = (blockIdx.x * WARPS + w) * NB + jj;

        // --- stage x_b (64x16 fp32 = 4KB, contiguous) into shared ---
        {
            const float4* xg = (const float4*)(x + (size_t)b * 1024);
            float4* xs = (float4*)sx;
            #pragma unroll
            for (int i = 0; i < 8; i++)
                xs[i * 32 + lane] = xg[i * 32 + lane];
        }

        // --- num_neighbors from L[b,0,:] (values are exactly 0.0/1.0) ---
        float Lv = 0.0f;
        if (lane < 16) Lv = L[(size_t)b * 256 + lane];
        unsigned msk = __ballot_sync(0xffffffffu, Lv >= 1.0f);
        float nn = (float)(__popc(msk) + 1);
        float rs = rsqrtf(nn);
        __syncwarp();

        // --- projections: lane r accumulates Q/K/V row r over d, packed x2 ---
        u64 q[8], k[8], v[8];
        #pragma unroll
        for (int p = 0; p < 8; p++) { q[p] = 0ull; k[p] = 0ull; v[p] = 0ull; }

        #pragma unroll 4
        for (int d = 0; d < 64; d++) {
            const ulonglong2* xr = (const ulonglong2*)(sx + d * 16);
            ulonglong2 xa = xr[0], xb = xr[1], xc = xr[2], xd = xr[3];
            u64 aq = dup2(sAq[d * 32 + lane]);
            u64 ak = dup2(sAk[d * 32 + lane]);
            u64 av = dup2(sAv[d * 32 + lane]);
            q[0] = ff2(aq, xa.x, q[0]); q[1] = ff2(aq, xa.y, q[1]);
            q[2] = ff2(aq, xb.x, q[2]); q[3] = ff2(aq, xb.y, q[3]);
            q[4] = ff2(aq, xc.x, q[4]); q[5] = ff2(aq, xc.y, q[5]);
            q[6] = ff2(aq, xd.x, q[6]); q[7] = ff2(aq, xd.y, q[7]);
            k[0] = ff2(ak, xa.x, k[0]); k[1] = ff2(ak, xa.y, k[1]);
            k[2] = ff2(ak, xb.x, k[2]); k[3] = ff2(ak, xb.y, k[3]);
            k[4] = ff2(ak, xc.x, k[4]); k[5] = ff2(ak, xc.y, k[5]);
            k[6] = ff2(ak, xd.x, k[6]); k[7] = ff2(ak, xd.y, k[7]);
            v[0] = ff2(av, xa.x, v[0]); v[1] = ff2(av, xa.y, v[1]);
            v[2] = ff2(av, xb.x, v[2]); v[3] = ff2(av, xb.y, v[3]);
            v[4] = ff2(av, xc.x, v[4]); v[5] = ff2(av, xc.y, v[5]);
            v[6] = ff2(av, xd.x, v[6]); v[7] = ff2(av, xd.y, v[7]);
        }

        // --- tanh; fold 1/sqrt(nn) into Q; publish K,V rows to shared ---
        {
            u64 rs2 = dup2(rs);
            #pragma unroll
            for (int p = 0; p < 8; p++) {
                float2 fq = un2(q[p]);
                q[p] = mul2(pk2(tanh_approx(fq.x), tanh_approx(fq.y)), rs2);
                float2 fk = un2(k[p]);
                *(u64*)(sK + lane * 18 + 2 * p) = pk2(tanh_approx(fk.x), tanh_approx(fk.y));
                float2 fv = un2(v[p]);
                *(u64*)(sV + lane * 18 + 2 * p) = pk2(tanh_approx(fv.x), tanh_approx(fv.y));
            }
        }
        __syncwarp();

        // --- fused scores + softmax-numerator + o accumulation ---
        // |score| <= n / sqrt(nn) <= 16 -> exp() safe without max subtraction.
        u64 o[8];
        #pragma unroll
        for (int p = 0; p < 8; p++) o[p] = 0ull;
        float esum = 0.0f;

        #pragma unroll 4
        for (int s = 0; s < 32; s++) {
            const u64* kr = (const u64*)(sK + s * 18);
            u64 acc = mul2(q[0], kr[0]);
            #pragma unroll
            for (int p = 1; p < 8; p++) acc = ff2(q[p], kr[p], acc);
            float2 a2 = un2(acc);
            float e = __expf(a2.x + a2.y);
            esum += e;
            u64 e2 = dup2(e);
            const u64* vr = (const u64*)(sV + s * 18);
            #pragma unroll
            for (int p = 0; p < 8; p++) o[p] = ff2(e2, vr[p], o[p]);
        }

        // --- contribution c[r][n] = (Ao[r]/esum) * o[r][n], reduce over r ---
        float coef = aor / esum;
        u64 c2 = dup2(coef);
        __syncwarp();                       // done reading sK rows
        #pragma unroll
        for (int p = 0; p < 8; p++)
            *(u64*)(sK + lane * 18 + 2 * p) = mul2(c2, o[p]);   // reuse sK
        __syncwarp();

        const int jn = lane & 15;
        float cs0 = 0.0f, cs1 = 0.0f;
        #pragma unroll
        for (int r = 0; r < 32; r += 2) {
            cs0 += sK[r * 18 + jn];
            cs1 += sK[(r + 1) * 18 + jn];
        }
        float z  = cs0 + cs1;
        float Rv = tanhf(z);                // accurate: feeds output directly
        float R2 = Rv * Rv;

        // row total across the 16 agent columns (lanes 0-15 / 16-31 mirrored)
        float tot = R2;
        tot += __shfl_xor_sync(0xffffffffu, tot, 8);
        tot += __shfl_xor_sync(0xffffffffu, tot, 4);
        tot += __shfl_xor_sync(0xffffffffu, tot, 2);
        tot += __shfl_xor_sync(0xffffffffu, tot, 1);

        const int ii = b & 15;
        if (lane < 16)
            out[(size_t)b * 16 + jn] = (jn == ii) ? tot : -R2;
        __syncwarp();
    }
}

extern "C" void kernel_launch(void* const* d_in, const int* in_sizes, int n_in,
                              void* d_out, int out_size)
{
    const float* x  = (const float*)d_in[0];
    const float* L  = (const float*)d_in[1];
    const float* Aq = (const float*)d_in[2];
    const float* Ak = (const float*)d_in[3];
    const float* Av = (const float*)d_in[4];
    const float* Ao = (const float*)d_in[5];
    float* out = (float*)d_out;

    int B = in_sizes[0] / (64 * 16);          // 65536
    int blocks = B / (WARPS * NB);            // 2048

    cudaFuncSetAttribute(att_mask_kernel,
                         cudaFuncAttributeMaxDynamicSharedMemorySize, SMEM_BYTES);
    att_mask_kernel<<<blocks, WARPS * 32, SMEM_BYTES>>>(x, L, Aq, Ak, Av, Ao, out);
}

// round 5
// speedup vs baseline: 1.0001x; 1.0001x over previous
#include <cuda_runtime.h>

// ---------------------------------------------------------------------------
// Att_mask: per batch item b (65536 of them):
//   Q = tanh(Aq @ x_b), K = tanh(Ak @ x_b), V = tanh(Av @ x_b)   ([32,16] each)
//   scores = Q K^T / sqrt(nn_b); attn = softmax(scores, axis=s)
//   o = attn @ V ; R = tanh(Ao @ o)  ([16])
//   out row (b = s*16+i): out[b,j] = (j==i) ? sum_j R2[j] : -R2[j],  R2 = R^2
//
// Strategy: one warp per batch item (lane = rank r), packed f32x2 FFMA
// (fma.rn.f32x2 -> FFMA2, 2x fp32 throughput), A matrices transposed in
// shared (conflict-free lane reads), x/K/V staged in per-warp shared.
// Online softmax (|score| <= 16 so exp never overflows; no max pass, no
// 32-register score array).
// ---------------------------------------------------------------------------

typedef unsigned long long u64;

__device__ __forceinline__ u64 ff2(u64 a, u64 b, u64 c) {
    u64 d; asm("fma.rn.f32x2 %0, %1, %2, %3;" : "=l"(d) : "l"(a), "l"(b), "l"(c)); return d;
}
__device__ __forceinline__ u64 mul2(u64 a, u64 b) {
    u64 d; asm("mul.rn.f32x2 %0, %1, %2;" : "=l"(d) : "l"(a), "l"(b)); return d;
}
__device__ __forceinline__ u64 dup2(float a) {
    u64 d; asm("mov.b64 %0, {%1, %1};" : "=l"(d) : "f"(a)); return d;
}
__device__ __forceinline__ float2 un2(u64 a) {
    float2 f; asm("mov.b64 {%0, %1}, %2;" : "=f"(f.x), "=f"(f.y) : "l"(a)); return f;
}
__device__ __forceinline__ u64 pk2(float x, float y) {
    u64 d; asm("mov.b64 %0, {%1, %2};" : "=l"(d) : "f"(x), "f"(y)); return d;
}
__device__ __forceinline__ float tanh_approx(float x) {
    float y; asm("tanh.approx.f32 %0, %1;" : "=f"(y) : "f"(x)); return y;
}

static constexpr int WARPS = 8;     // warps per block
static constexpr int NB    = 4;     // batch items per warp
// shared layout (floats):
//   sAq[64*32] sAk[64*32] sAv[64*32] sAo[32]   = 6176
//   per warp: x[64*16]=1024, K[32*18]=576, V[32*18]=576  -> 2176
static constexpr int A_FLOATS  = 3 * 2048 + 32;       // 6176
static constexpr int PW_FLOATS = 1024 + 576 + 576;    // 2176
static constexpr int SMEM_BYTES = (A_FLOATS + WARPS * PW_FLOATS) * 4;  // 94336

__global__ void __launch_bounds__(WARPS * 32, 2)
att_mask_kernel(const float* __restrict__ x, const float* __restrict__ L,
                const float* __restrict__ Aq, const float* __restrict__ Ak,
                const float* __restrict__ Av, const float* __restrict__ Ao,
                float* __restrict__ out)
{
    extern __shared__ float smem[];
    float* sAq = smem;            // [64][32], sAq[d*32+r] = Aq[r*64+d]
    float* sAk = smem + 2048;
    float* sAv = smem + 4096;
    float* sAo = smem + 6144;     // [32]

    const int tid = threadIdx.x;

    // Load A transposed: conflict-free broadcast-free lane-indexed reads later.
    for (int i = tid; i < 2048; i += WARPS * 32) {
        int d = i >> 5, r = i & 31;
        sAq[i] = Aq[r * 64 + d];
        sAk[i] = Ak[r * 64 + d];
        sAv[i] = Av[r * 64 + d];
    }
    if (tid < 32) sAo[tid] = Ao[tid];
    __syncthreads();

    const int w    = tid >> 5;
    const int lane = tid & 31;

    float* sx = smem + A_FLOATS + w * PW_FLOATS;   // [64][16]
    float* sK = sx + 1024;                         // [32] rows, stride 18
    float* sV = sK + 576;                          // [32] rows, stride 18

    const float aor = sAo[lane];

    for (int jj = 0; jj < NB; jj++) {
        const int b = (blockIdx.x * WARPS + w) * NB + jj;

        // --- stage x_b (64x16 fp32 = 4KB, contiguous) into shared ---
        {
            const float4* xg = (const float4*)(x + (size_t)b * 1024);
            float4* xs = (float4*)sx;
            #pragma unroll
            for (int i = 0; i < 8; i++)
                xs[i * 32 + lane] = xg[i * 32 + lane];
        }

        // --- num_neighbors from L[b,0,:] (values are exactly 0.0/1.0) ---
        float Lv = 0.0f;
        if (lane < 16) Lv = L[(size_t)b * 256 + lane];
        unsigned msk = __ballot_sync(0xffffffffu, Lv >= 1.0f);
        float nn = (float)(__popc(msk) + 1);
        float rs = rsqrtf(nn);
        __syncwarp();

        // --- projections: lane r accumulates Q/K/V row r over d, packed x2 ---
        u64 q[8], k[8], v[8];
        #pragma unroll
        for (int p = 0; p < 8; p++) { q[p] = 0ull; k[p] = 0ull; v[p] = 0ull; }

        #pragma unroll 4
        for (int d = 0; d < 64; d++) {
            const ulonglong2* xr = (const ulonglong2*)(sx + d * 16);
            ulonglong2 xa = xr[0], xb = xr[1], xc = xr[2], xd = xr[3];
            u64 aq = dup2(sAq[d * 32 + lane]);
            u64 ak = dup2(sAk[d * 32 + lane]);
            u64 av = dup2(sAv[d * 32 + lane]);
            q[0] = ff2(aq, xa.x, q[0]); q[1] = ff2(aq, xa.y, q[1]);
            q[2] = ff2(aq, xb.x, q[2]); q[3] = ff2(aq, xb.y, q[3]);
            q[4] = ff2(aq, xc.x, q[4]); q[5] = ff2(aq, xc.y, q[5]);
            q[6] = ff2(aq, xd.x, q[6]); q[7] = ff2(aq, xd.y, q[7]);
            k[0] = ff2(ak, xa.x, k[0]); k[1] = ff2(ak, xa.y, k[1]);
            k[2] = ff2(ak, xb.x, k[2]); k[3] = ff2(ak, xb.y, k[3]);
            k[4] = ff2(ak, xc.x, k[4]); k[5] = ff2(ak, xc.y, k[5]);
            k[6] = ff2(ak, xd.x, k[6]); k[7] = ff2(ak, xd.y, k[7]);
            v[0] = ff2(av, xa.x, v[0]); v[1] = ff2(av, xa.y, v[1]);
            v[2] = ff2(av, xb.x, v[2]); v[3] = ff2(av, xb.y, v[3]);
            v[4] = ff2(av, xc.x, v[4]); v[5] = ff2(av, xc.y, v[5]);
            v[6] = ff2(av, xd.x, v[6]); v[7] = ff2(av, xd.y, v[7]);
        }

        // --- tanh; fold 1/sqrt(nn) into Q; publish K,V rows to shared ---
        {
            u64 rs2 = dup2(rs);
            #pragma unroll
            for (int p = 0; p < 8; p++) {
                float2 fq = un2(q[p]);
                q[p] = mul2(pk2(tanh_approx(fq.x), tanh_approx(fq.y)), rs2);
                float2 fk = un2(k[p]);
                *(u64*)(sK + lane * 18 + 2 * p) = pk2(tanh_approx(fk.x), tanh_approx(fk.y));
                float2 fv = un2(v[p]);
                *(u64*)(sV + lane * 18 + 2 * p) = pk2(tanh_approx(fv.x), tanh_approx(fv.y));
            }
        }
        __syncwarp();

        // --- fused scores + softmax-numerator + o accumulation ---
        // |score| <= n / sqrt(nn) <= 16 -> exp() safe without max subtraction.
        u64 o[8];
        #pragma unroll
        for (int p = 0; p < 8; p++) o[p] = 0ull;
        float esum = 0.0f;

        #pragma unroll 4
        for (int s = 0; s < 32; s++) {
            const u64* kr = (const u64*)(sK + s * 18);
            u64 acc = mul2(q[0], kr[0]);
            #pragma unroll
            for (int p = 1; p < 8; p++) acc = ff2(q[p], kr[p], acc);
            float2 a2 = un2(acc);
            float e = __expf(a2.x + a2.y);
            esum += e;
            u64 e2 = dup2(e);
            const u64* vr = (const u64*)(sV + s * 18);
            #pragma unroll
            for (int p = 0; p < 8; p++) o[p] = ff2(e2, vr[p], o[p]);
        }

        // --- contribution c[r][n] = (Ao[r]/esum) * o[r][n], reduce over r ---
        float coef = aor / esum;
        u64 c2 = dup2(coef);
        __syncwarp();                       // done reading sK rows
        #pragma unroll
        for (int p = 0; p < 8; p++)
            *(u64*)(sK + lane * 18 + 2 * p) = mul2(c2, o[p]);   // reuse sK
        __syncwarp();

        const int jn = lane & 15;
        float cs0 = 0.0f, cs1 = 0.0f;
        #pragma unroll
        for (int r = 0; r < 32; r += 2) {
            cs0 += sK[r * 18 + jn];
            cs1 += sK[(r + 1) * 18 + jn];
        }
        float z  = cs0 + cs1;
        float Rv = tanhf(z);                // accurate: feeds output directly
        float R2 = Rv * Rv;

        // row total across the 16 agent columns (lanes 0-15 / 16-31 mirrored)
        float tot = R2;
        tot += __shfl_xor_sync(0xffffffffu, tot, 8);
        tot += __shfl_xor_sync(0xffffffffu, tot, 4);
        tot += __shfl_xor_sync(0xffffffffu, tot, 2);
        tot += __shfl_xor_sync(0xffffffffu, tot, 1);

        const int ii = b & 15;
        if (lane < 16)
            out[(size_t)b * 16 + jn] = (jn == ii) ? tot : -R2;
        __syncwarp();
    }
}

extern "C" void kernel_launch(void* const* d_in, const int* in_sizes, int n_in,
                              void* d_out, int out_size)
{
    const float* x  = (const float*)d_in[0];
    const float* L  = (const float*)d_in[1];
    const float* Aq = (const float*)d_in[2];
    const float* Ak = (const float*)d_in[3];
    const float* Av = (const float*)d_in[4];
    const float* Ao = (const float*)d_in[5];
    float* out = (float*)d_out;

    int B = in_sizes[0] / (64 * 16);          // 65536
    int blocks = B / (WARPS * NB);            // 2048

    cudaFuncSetAttribute(att_mask_kernel,
                         cudaFuncAttributeMaxDynamicSharedMemorySize, SMEM_BYTES);
    att_mask_kernel<<<blocks, WARPS * 32, SMEM_BYTES>>>(x, L, Aq, Ak, Av, Ao, out);
}